// round 4
// baseline (speedup 1.0000x reference)
#include <cuda_runtime.h>

#define BB 4
#define SS 2048
#define HH 16
#define DHD 64
#define DM 1024
#define PP (BB*SS)      // 8192 total positions
#define PITCH 68        // smem row pitch (floats): 16B-aligned rows, conflict-light

// Scratch (static device arrays -- no allocation APIs anywhere)
__device__ float g_qkv[3][PP*DM];   // q,k,v in (b,s,h*64+d) layout
__device__ float g_attn[PP*DM];    // attention output, same layout

// ---------------------------------------------------------------------------
// QKV projection: out[p, h*64+d] = sum_m x[p,m] * W[h,m,d] + b[h,d]
// One 64-wide column tile == one head => W tile is a contiguous 64x64 block.
// ---------------------------------------------------------------------------
__global__ __launch_bounds__(256) void proj_kernel(const float* __restrict__ x,
                                                   const float* __restrict__ W,
                                                   const float* __restrict__ bias,
                                                   int which)
{
    __shared__ float As[16][64];   // A tile transposed: As[k][p]
    __shared__ float Bs[16][64];   // B tile: Bs[k][d]
    float* out = g_qkv[which];

    const int h  = blockIdx.y;
    const int p0 = blockIdx.x * 64;
    const float* Bsrc = W + h * (DM * DHD);   // (1024 x 64) row-major
    const int tid  = threadIdx.x;
    const int tx   = tid & 15, ty = tid >> 4;
    const int arow = tid >> 2;            // 0..63
    const int akc  = (tid & 3) * 4;       // 0,4,8,12

    float acc[4][4] = {};

    for (int k0 = 0; k0 < DM; k0 += 16) {
        float4 av = *(const float4*)(x + (p0 + arow) * DM + k0 + akc);
        float4 bv = *(const float4*)(Bsrc + k0 * 64 + tid * 4);
        __syncthreads();
        As[akc + 0][arow] = av.x;
        As[akc + 1][arow] = av.y;
        As[akc + 2][arow] = av.z;
        As[akc + 3][arow] = av.w;
        ((float4*)Bs)[tid] = bv;
        __syncthreads();
        #pragma unroll
        for (int k = 0; k < 16; k++) {
            float4 a4 = *(const float4*)&As[k][ty * 4];
            float4 b4 = *(const float4*)&Bs[k][tx * 4];
            float a[4] = {a4.x, a4.y, a4.z, a4.w};
            float b[4] = {b4.x, b4.y, b4.z, b4.w};
            #pragma unroll
            for (int i = 0; i < 4; i++)
                #pragma unroll
                for (int j = 0; j < 4; j++)
                    acc[i][j] += a[i] * b[j];
        }
    }

    #pragma unroll
    for (int i = 0; i < 4; i++) {
        const int p = p0 + ty * 4 + i;
        #pragma unroll
        for (int j = 0; j < 4; j++) {
            const int n = tx * 4 + j;
            out[p * DM + h * 64 + n] = acc[i][j] + bias[h * 64 + n];
        }
    }
}

// ---------------------------------------------------------------------------
// Flash attention (fp32): one block per (b, h, q-tile of 64). Tk = 64.
// Smem: Qt (d-major), Kt (d-major, reused for P k-major), Vs (k-major).
// ---------------------------------------------------------------------------
__global__ __launch_bounds__(256) void attn_kernel()
{
    extern __shared__ float sm[];
    float* Qt = sm;                  // Qt[d*PITCH + r]
    float* Kt = sm + 64 * PITCH;     // Kt[d*PITCH + c]  -> later Pt[k*PITCH + r]
    float* Vs = sm + 2 * 64 * PITCH; // Vs[k*PITCH + d]

    const float* gq = g_qkv[0];
    const float* gk = g_qkv[1];
    const float* gv = g_qkv[2];

    const int qt = blockIdx.x;
    const int bh = blockIdx.y;
    const int b  = bh >> 4, h = bh & 15;
    const int q0 = qt * 64;
    const int tid = threadIdx.x;
    const int tx  = tid & 15, ty = tid >> 4;
    const int lrow = tid >> 2;          // 0..63: row within tile for loads
    const int ld0  = (tid & 3) * 16;    // 16 d-elements per thread

    // Load Q tile transposed (d-major)
    {
        const float* src = gq + (b * SS + q0 + lrow) * DM + h * 64;
        #pragma unroll
        for (int u = 0; u < 4; u++) {
            float4 v = *(const float4*)(src + ld0 + u * 4);
            Qt[(ld0 + u * 4 + 0) * PITCH + lrow] = v.x;
            Qt[(ld0 + u * 4 + 1) * PITCH + lrow] = v.y;
            Qt[(ld0 + u * 4 + 2) * PITCH + lrow] = v.z;
            Qt[(ld0 + u * 4 + 3) * PITCH + lrow] = v.w;
        }
    }

    float m[4], l[4], acc[4][4];
    #pragma unroll
    for (int i = 0; i < 4; i++) {
        m[i] = -1e30f; l[i] = 0.0f;
        #pragma unroll
        for (int j = 0; j < 4; j++) acc[i][j] = 0.0f;
    }

    for (int kt = 0; kt <= qt; kt++) {
        __syncthreads();   // previous iteration's P/V reads complete
        const int k0 = kt * 64;
        {
            const float* ksrc = gk + (b * SS + k0 + lrow) * DM + h * 64;
            const float* vsrc = gv + (b * SS + k0 + lrow) * DM + h * 64;
            #pragma unroll
            for (int u = 0; u < 4; u++) {
                float4 kv = *(const float4*)(ksrc + ld0 + u * 4);
                Kt[(ld0 + u * 4 + 0) * PITCH + lrow] = kv.x;
                Kt[(ld0 + u * 4 + 1) * PITCH + lrow] = kv.y;
                Kt[(ld0 + u * 4 + 2) * PITCH + lrow] = kv.z;
                Kt[(ld0 + u * 4 + 3) * PITCH + lrow] = kv.w;
                *(float4*)&Vs[lrow * PITCH + ld0 + u * 4] =
                    *(const float4*)(vsrc + ld0 + u * 4);
            }
        }
        __syncthreads();

        // S = Q K^T (64x64), 4x4 per thread
        float s[4][4] = {};
        #pragma unroll 8
        for (int d = 0; d < 64; d++) {
            float4 q4 = *(const float4*)&Qt[d * PITCH + ty * 4];
            float4 k4 = *(const float4*)&Kt[d * PITCH + tx * 4];
            float qa[4] = {q4.x, q4.y, q4.z, q4.w};
            float kb[4] = {k4.x, k4.y, k4.z, k4.w};
            #pragma unroll
            for (int i = 0; i < 4; i++)
                #pragma unroll
                for (int j = 0; j < 4; j++)
                    s[i][j] += qa[i] * kb[j];
        }

        // scale + causal mask + streaming softmax update
        #pragma unroll
        for (int i = 0; i < 4; i++) {
            const int q = q0 + ty * 4 + i;
            float mx = -1e30f;
            #pragma unroll
            for (int j = 0; j < 4; j++) {
                const int kk = k0 + tx * 4 + j;
                float v = s[i][j] * 0.125f;
                if (kk > q) v = -100000.0f;
                s[i][j] = v;
                mx = fmaxf(mx, v);
            }
            #pragma unroll
            for (int off = 8; off; off >>= 1)
                mx = fmaxf(mx, __shfl_xor_sync(0xffffffffu, mx, off, 16));
            const float newm = fmaxf(m[i], mx);
            const float fac  = __expf(m[i] - newm);
            float sum = 0.0f;
            #pragma unroll
            for (int j = 0; j < 4; j++) {
                const float p = __expf(s[i][j] - newm);
                s[i][j] = p;
                sum += p;
            }
            #pragma unroll
            for (int off = 8; off; off >>= 1)
                sum += __shfl_xor_sync(0xffffffffu, sum, off, 16);
            l[i] = l[i] * fac + sum;
            m[i] = newm;
            #pragma unroll
            for (int j = 0; j < 4; j++) acc[i][j] *= fac;
        }

        __syncthreads();   // everyone done reading Kt as K
        // store P transposed into Kt: Pt[c*PITCH + r]
        #pragma unroll
        for (int i = 0; i < 4; i++)
            #pragma unroll
            for (int j = 0; j < 4; j++)
                Kt[(tx * 4 + j) * PITCH + ty * 4 + i] = s[i][j];
        __syncthreads();

        // acc += P @ V
        #pragma unroll 8
        for (int kk = 0; kk < 64; kk++) {
            float4 p4 = *(const float4*)&Kt[kk * PITCH + ty * 4];
            float4 v4 = *(const float4*)&Vs[kk * PITCH + tx * 4];
            float pa[4] = {p4.x, p4.y, p4.z, p4.w};
            float vb[4] = {v4.x, v4.y, v4.z, v4.w};
            #pragma unroll
            for (int i = 0; i < 4; i++)
                #pragma unroll
                for (int j = 0; j < 4; j++)
                    acc[i][j] += pa[i] * vb[j];
        }
    }

    // normalize + write (b,s,h*64+d)
    #pragma unroll
    for (int i = 0; i < 4; i++) {
        const float inv = 1.0f / l[i];
        const int p = b * SS + q0 + ty * 4 + i;
        #pragma unroll
        for (int j = 0; j < 4; j++)
            g_attn[p * DM + h * 64 + tx * 4 + j] = acc[i][j] * inv;
    }
}

// ---------------------------------------------------------------------------
// O projection: out[p,m] = sum_k attn[p,k] * O_w[k,m] + O_b[m]
// (O_w[h,d,m] with k = h*64+d is plain row-major 1024x1024)
// ---------------------------------------------------------------------------
__global__ __launch_bounds__(256) void oproj_kernel(const float* __restrict__ Bw,
                                                    const float* __restrict__ bias,
                                                    float* __restrict__ out)
{
    __shared__ float As[16][64];
    __shared__ float Bs[16][64];
    const float* A = g_attn;

    const int n0 = blockIdx.y * 64;
    const int p0 = blockIdx.x * 64;
    const int tid  = threadIdx.x;
    const int tx   = tid & 15, ty = tid >> 4;
    const int arow = tid >> 2;
    const int akc  = (tid & 3) * 4;
    const int brow = tid >> 4;           // 0..15
    const int bcol = (tid & 15) * 4;     // 0..60

    float acc[4][4] = {};

    for (int k0 = 0; k0 < DM; k0 += 16) {
        float4 av = *(const float4*)(A + (p0 + arow) * DM + k0 + akc);
        float4 bv = *(const float4*)(Bw + (k0 + brow) * DM + n0 + bcol);
        __syncthreads();
        As[akc + 0][arow] = av.x;
        As[akc + 1][arow] = av.y;
        As[akc + 2][arow] = av.z;
        As[akc + 3][arow] = av.w;
        *(float4*)&Bs[brow][bcol] = bv;
        __syncthreads();
        #pragma unroll
        for (int k = 0; k < 16; k++) {
            float4 a4 = *(const float4*)&As[k][ty * 4];
            float4 b4 = *(const float4*)&Bs[k][tx * 4];
            float a[4] = {a4.x, a4.y, a4.z, a4.w};
            float b[4] = {b4.x, b4.y, b4.z, b4.w};
            #pragma unroll
            for (int i = 0; i < 4; i++)
                #pragma unroll
                for (int j = 0; j < 4; j++)
                    acc[i][j] += a[i] * b[j];
        }
    }

    #pragma unroll
    for (int i = 0; i < 4; i++) {
        const int p = p0 + ty * 4 + i;
        #pragma unroll
        for (int j = 0; j < 4; j++) {
            const int n = n0 + tx * 4 + j;
            out[p * DM + n] = acc[i][j] + bias[n];
        }
    }
}

extern "C" void kernel_launch(void* const* d_in, const int* in_sizes, int n_in,
                              void* d_out, int out_size)
{
    const float* x  = (const float*)d_in[0];
    const float* Qw = (const float*)d_in[1];
    const float* Qb = (const float*)d_in[2];
    const float* Kw = (const float*)d_in[3];
    const float* Kb = (const float*)d_in[4];
    const float* Vw = (const float*)d_in[5];
    const float* Vb = (const float*)d_in[6];
    const float* Ow = (const float*)d_in[7];
    const float* Ob = (const float*)d_in[8];
    float* out = (float*)d_out;

    const int attn_smem = 3 * 64 * PITCH * (int)sizeof(float);   // 52224 B
    cudaFuncSetAttribute(attn_kernel,
                         cudaFuncAttributeMaxDynamicSharedMemorySize, attn_smem);

    dim3 gproj(PP / 64, HH);       // 128 x 16
    proj_kernel<<<gproj, 256>>>(x, Qw, Qb, 0);
    proj_kernel<<<gproj, 256>>>(x, Kw, Kb, 1);
    proj_kernel<<<gproj, 256>>>(x, Vw, Vb, 2);

    dim3 gattn(SS / 64, BB * HH);  // 32 x 64
    attn_kernel<<<gattn, 256, attn_smem>>>();

    dim3 goproj(PP / 64, DM / 64); // 128 x 16
    oproj_kernel<<<goproj, 256>>>(Ow, Ob, out);
}

// round 9
// speedup vs baseline: 2.4945x; 2.4945x over previous
#include <cuda_runtime.h>
#include <cstdint>

#define BB 4
#define SS 2048
#define HH 16
#define DM 1024
#define PP (BB*SS)      // 8192 total positions

// Scratch (static device arrays -- no allocation APIs anywhere)
__device__ float g_qkv[3][PP*DM];   // q,k,v in (b,s,h*64+d) layout
__device__ float g_attn[PP*DM];     // attention output, same layout

// ---------------------------------------------------------------------------
// tf32 helpers (baseline PTX: sm_80+, accepted by the sm_103 target)
// ---------------------------------------------------------------------------
__device__ __forceinline__ uint32_t tf32r(float x) {
    uint32_t r;
    asm("cvt.rna.tf32.f32 %0, %1;" : "=r"(r) : "f"(x));
    return r;
}

// D += A * B  (m16n8k8, tf32 in, fp32 accum)
__device__ __forceinline__ void mma8(float* c, const uint32_t* a,
                                     uint32_t b0, uint32_t b1) {
    asm volatile(
        "mma.sync.aligned.m16n8k8.row.col.f32.tf32.tf32.f32 "
        "{%0,%1,%2,%3}, {%4,%5,%6,%7}, {%8,%9}, {%0,%1,%2,%3};"
        : "+f"(c[0]), "+f"(c[1]), "+f"(c[2]), "+f"(c[3])
        : "r"(a[0]), "r"(a[1]), "r"(a[2]), "r"(a[3]), "r"(b0), "r"(b1));
}

// ===========================================================================
// Projection GEMM via mma.sync tf32.  C tile 128x128, K-step 16, double-buffered.
//   mode 0 (QKV fused): A = x, B = per-(which,head) 1024x64 blocks -> g_qkv
//   mode 1 (O-proj):    A = g_attn, B = Ow (1024x1024 row-major)   -> d_out
// Smem layout: As[k][m], Bs[k][n], pitch 140 (140 mod 32 = 12 -> the 4 k-phases
// of fragment loads land on disjoint bank groups).
// ===========================================================================
#define GPITCH 140

__global__ __launch_bounds__(256, 2) void gemm_mma(
    const float* __restrict__ A,
    const float* __restrict__ W0, const float* __restrict__ W1,
    const float* __restrict__ W2,
    const float* __restrict__ B0, const float* __restrict__ B1,
    const float* __restrict__ B2,
    float* __restrict__ oout, int mode)
{
    __shared__ uint32_t As[2][16][GPITCH];
    __shared__ uint32_t Bs[2][16][GPITCH];

    const int tid  = threadIdx.x;
    const int lane = tid & 31, wid = tid >> 5;
    const int wm = wid & 1, wn = wid >> 1;        // warp grid 2(m) x 4(n)
    const int g  = lane >> 2, qd = lane & 3;
    const int p0 = blockIdx.x * 128, nt = blockIdx.y;

    const float *Ain, *W, *bias;
    float* outp;
    int cw;
    if (mode == 0) {
        const int which = nt >> 3;
        W    = (which == 0) ? W0 : (which == 1) ? W1 : W2;
        bias = (which == 0) ? B0 : (which == 1) ? B1 : B2;
        outp = g_qkv[which];
        cw = (nt & 7) * 128;
        Ain = A;
    } else {
        W = W0; bias = B0; outp = oout;
        cw = nt * 128;
        Ain = g_attn;
    }

    float4 aR[2], bR[2];

    auto ldAB = [&](int k0) {
        #pragma unroll
        for (int q = 0; q < 2; q++) {
            const int u = tid + q * 256;
            const int r = u >> 2, kg = u & 3;          // A: 128 rows x 4 k-quads
            aR[q] = *(const float4*)(Ain + (size_t)(p0 + r) * DM + k0 + kg * 4);
            const int kc = u >> 5, n4 = u & 31;        // B: 16 k x 32 n-quads
            const float* bp;
            if (mode == 0) {
                const int c = cw + n4 * 4;
                bp = W + (size_t)(c >> 6) * (DM * 64) + (size_t)(k0 + kc) * 64 + (c & 63);
            } else {
                bp = W + (size_t)(k0 + kc) * DM + cw + n4 * 4;
            }
            bR[q] = *(const float4*)bp;
        }
    };
    auto stAB = [&](int buf) {
        #pragma unroll
        for (int q = 0; q < 2; q++) {
            const int u = tid + q * 256;
            const int r = u >> 2, kg = u & 3;
            As[buf][kg * 4 + 0][r] = tf32r(aR[q].x);
            As[buf][kg * 4 + 1][r] = tf32r(aR[q].y);
            As[buf][kg * 4 + 2][r] = tf32r(aR[q].z);
            As[buf][kg * 4 + 3][r] = tf32r(aR[q].w);
            const int kc = u >> 5, n4 = u & 31;
            uint32_t* d = &Bs[buf][kc][n4 * 4];
            d[0] = tf32r(bR[q].x); d[1] = tf32r(bR[q].y);
            d[2] = tf32r(bR[q].z); d[3] = tf32r(bR[q].w);
        }
    };

    float c[4][4][4] = {};

    ldAB(0);
    stAB(0);
    __syncthreads();

    for (int it = 0; it < 64; it++) {
        const int buf = it & 1;
        if (it < 63) ldAB((it + 1) * 16);
        #pragma unroll
        for (int k8 = 0; k8 < 16; k8 += 8) {
            uint32_t a[4][4], b[4][2];
            #pragma unroll
            for (int mt = 0; mt < 4; mt++) {
                const int r = wm * 64 + mt * 16 + g;
                a[mt][0] = As[buf][k8 + qd][r];
                a[mt][1] = As[buf][k8 + qd][r + 8];
                a[mt][2] = As[buf][k8 + qd + 4][r];
                a[mt][3] = As[buf][k8 + qd + 4][r + 8];
            }
            #pragma unroll
            for (int nn = 0; nn < 4; nn++) {
                const int ncol = wn * 32 + nn * 8 + g;
                b[nn][0] = Bs[buf][k8 + qd][ncol];
                b[nn][1] = Bs[buf][k8 + qd + 4][ncol];
            }
            #pragma unroll
            for (int mt = 0; mt < 4; mt++)
                #pragma unroll
                for (int nn = 0; nn < 4; nn++)
                    mma8(c[mt][nn], a[mt], b[nn][0], b[nn][1]);
        }
        if (it < 63) stAB(buf ^ 1);
        __syncthreads();
    }

    // Epilogue: fp32 accum + bias, float2 stores
    #pragma unroll
    for (int mt = 0; mt < 4; mt++) {
        const int row = p0 + wm * 64 + mt * 16 + g;
        #pragma unroll
        for (int nn = 0; nn < 4; nn++) {
            const int col = cw + wn * 32 + nn * 8 + 2 * qd;
            const float2 bv = *(const float2*)(bias + col);
            float2 v0, v1;
            v0.x = c[mt][nn][0] + bv.x; v0.y = c[mt][nn][1] + bv.y;
            v1.x = c[mt][nn][2] + bv.x; v1.y = c[mt][nn][3] + bv.y;
            *(float2*)(outp + (size_t)row * DM + col) = v0;
            *(float2*)(outp + (size_t)(row + 8) * DM + col) = v1;
        }
    }
}

// ===========================================================================
// Flash attention via mma.sync tf32.
// Block = (b, h, 64-q-tile), 128 thr = 4 warps; warp w owns q rows 16w..16w+15.
// Q fragments preloaded to registers (scaled by 1/8). K tile d-major (B frags
// for QK^T), V tile k-major (B frags for PV). P converted C-frag -> A-frag
// entirely with shfl (no smem round trip, no extra barriers).
// Smem pitch 72 (72 mod 32 = 8 -> 4 k-phases on disjoint bank groups).
// ===========================================================================
#define KP 72

__global__ __launch_bounds__(128) void attn_mma()
{
    __shared__ uint32_t Kt[64][KP];   // [d][kpos] tf32 bits (also Q staging [d][q])
    __shared__ uint32_t Vs[64][KP];   // [kpos][d] tf32 bits

    const int tid = threadIdx.x, lane = tid & 31, wid = tid >> 5;
    const int g = lane >> 2, qd = lane & 3;
    const int qt = blockIdx.x, bh = blockIdx.y;
    const int b = bh >> 4, h = bh & 15;
    const int q0 = qt * 64;
    const int lrow = tid >> 1, half = tid & 1;

    const float* gq = g_qkv[0];
    const float* gk = g_qkv[1];
    const float* gv = g_qkv[2];

    // Stage Q (pre-scaled by 1/sqrt(64)) into Kt as [d][q]
    {
        const float* src = gq + (size_t)(b * SS + q0 + lrow) * DM + h * 64 + half * 32;
        #pragma unroll
        for (int j = 0; j < 8; j++) {
            float4 v = *(const float4*)(src + j * 4);
            const int d = half * 32 + j * 4;
            Kt[d + 0][lrow] = tf32r(v.x * 0.125f);
            Kt[d + 1][lrow] = tf32r(v.y * 0.125f);
            Kt[d + 2][lrow] = tf32r(v.z * 0.125f);
            Kt[d + 3][lrow] = tf32r(v.w * 0.125f);
        }
    }
    __syncthreads();

    // Q fragments: 8 k8-steps x 4 regs, resident for the whole block
    uint32_t qa[8][4];
    {
        const int r = wid * 16 + g;
        #pragma unroll
        for (int t = 0; t < 8; t++) {
            qa[t][0] = Kt[t * 8 + qd][r];
            qa[t][1] = Kt[t * 8 + qd][r + 8];
            qa[t][2] = Kt[t * 8 + qd + 4][r];
            qa[t][3] = Kt[t * 8 + qd + 4][r + 8];
        }
    }

    float m0 = -1e30f, m1 = -1e30f, l0 = 0.f, l1 = 0.f;
    float acc[8][4] = {};

    for (int kt = 0; kt <= qt; kt++) {
        __syncthreads();   // qa loads done / previous tile's smem reads done
        const int k0 = kt * 64;
        {
            const float* ks = gk + (size_t)(b * SS + k0 + lrow) * DM + h * 64 + half * 32;
            const float* vs = gv + (size_t)(b * SS + k0 + lrow) * DM + h * 64 + half * 32;
            #pragma unroll
            for (int j = 0; j < 8; j++) {
                float4 kv = *(const float4*)(ks + j * 4);
                const int d = half * 32 + j * 4;
                Kt[d + 0][lrow] = tf32r(kv.x);
                Kt[d + 1][lrow] = tf32r(kv.y);
                Kt[d + 2][lrow] = tf32r(kv.z);
                Kt[d + 3][lrow] = tf32r(kv.w);
                float4 vv = *(const float4*)(vs + j * 4);
                uint4 t4;
                t4.x = tf32r(vv.x); t4.y = tf32r(vv.y);
                t4.z = tf32r(vv.z); t4.w = tf32r(vv.w);
                *(uint4*)&Vs[lrow][d] = t4;
            }
        }
        __syncthreads();

        // S = (Q/8) K^T : c[nt] covers k-cols nt*8..nt*8+7
        float c[8][4] = {};
        #pragma unroll
        for (int nt = 0; nt < 8; nt++) {
            #pragma unroll
            for (int t = 0; t < 8; t++) {
                uint32_t b0 = Kt[t * 8 + qd][nt * 8 + g];
                uint32_t b1 = Kt[t * 8 + qd + 4][nt * 8 + g];
                mma8(c[nt], qa[t], b0, b1);
            }
        }

        // Causal mask (only the diagonal tile needs it)
        if (kt == qt) {
            const int qg0 = q0 + wid * 16 + g, qg1 = qg0 + 8;
            #pragma unroll
            for (int nt = 0; nt < 8; nt++) {
                const int c0 = k0 + nt * 8 + 2 * qd;
                if (c0     > qg0) c[nt][0] = -100000.f;
                if (c0 + 1 > qg0) c[nt][1] = -100000.f;
                if (c0     > qg1) c[nt][2] = -100000.f;
                if (c0 + 1 > qg1) c[nt][3] = -100000.f;
            }
        }

        // Online softmax (rows r0 = g, r1 = g+8; quad {qd} spans the 64 cols)
        float rmax0 = -1e30f, rmax1 = -1e30f;
        #pragma unroll
        for (int nt = 0; nt < 8; nt++) {
            rmax0 = fmaxf(rmax0, fmaxf(c[nt][0], c[nt][1]));
            rmax1 = fmaxf(rmax1, fmaxf(c[nt][2], c[nt][3]));
        }
        rmax0 = fmaxf(rmax0, __shfl_xor_sync(0xffffffffu, rmax0, 1));
        rmax0 = fmaxf(rmax0, __shfl_xor_sync(0xffffffffu, rmax0, 2));
        rmax1 = fmaxf(rmax1, __shfl_xor_sync(0xffffffffu, rmax1, 1));
        rmax1 = fmaxf(rmax1, __shfl_xor_sync(0xffffffffu, rmax1, 2));

        const float nm0 = fmaxf(m0, rmax0), nm1 = fmaxf(m1, rmax1);
        const float f0 = __expf(m0 - nm0), f1 = __expf(m1 - nm1);
        float s0 = 0.f, s1 = 0.f;
        #pragma unroll
        for (int nt = 0; nt < 8; nt++) {
            c[nt][0] = __expf(c[nt][0] - nm0); s0 += c[nt][0];
            c[nt][1] = __expf(c[nt][1] - nm0); s0 += c[nt][1];
            c[nt][2] = __expf(c[nt][2] - nm1); s1 += c[nt][2];
            c[nt][3] = __expf(c[nt][3] - nm1); s1 += c[nt][3];
        }
        s0 += __shfl_xor_sync(0xffffffffu, s0, 1);
        s0 += __shfl_xor_sync(0xffffffffu, s0, 2);
        s1 += __shfl_xor_sync(0xffffffffu, s1, 1);
        s1 += __shfl_xor_sync(0xffffffffu, s1, 2);
        l0 = l0 * f0 + s0; l1 = l1 * f1 + s1;
        m0 = nm0; m1 = nm1;
        #pragma unroll
        for (int dt = 0; dt < 8; dt++) {
            acc[dt][0] *= f0; acc[dt][1] *= f0;
            acc[dt][2] *= f1; acc[dt][3] *= f1;
        }

        // PV: convert C-frag tile t -> A-frag (k = t*8..t*8+7) via shfl
        const int h1l = (lane & ~3) | (qd >> 1);
        const int h2l = h1l + 2;
        const bool odd = (qd & 1) != 0;
        #pragma unroll
        for (int t = 0; t < 8; t++) {
            float x0 = __shfl_sync(0xffffffffu, c[t][0], h1l);
            float x1 = __shfl_sync(0xffffffffu, c[t][1], h1l);
            float y0 = __shfl_sync(0xffffffffu, c[t][0], h2l);
            float y1 = __shfl_sync(0xffffffffu, c[t][1], h2l);
            float z0 = __shfl_sync(0xffffffffu, c[t][2], h1l);
            float z1 = __shfl_sync(0xffffffffu, c[t][3], h1l);
            float w0 = __shfl_sync(0xffffffffu, c[t][2], h2l);
            float w1 = __shfl_sync(0xffffffffu, c[t][3], h2l);
            uint32_t a[4];
            a[0] = tf32r(odd ? x1 : x0);   // (r0, k=qd)
            a[1] = tf32r(odd ? z1 : z0);   // (r1, k=qd)
            a[2] = tf32r(odd ? y1 : y0);   // (r0, k=qd+4)
            a[3] = tf32r(odd ? w1 : w0);   // (r1, k=qd+4)
            #pragma unroll
            for (int dt = 0; dt < 8; dt++) {
                uint32_t b0 = Vs[t * 8 + qd][dt * 8 + g];
                uint32_t b1 = Vs[t * 8 + qd + 4][dt * 8 + g];
                mma8(acc[dt], a, b0, b1);
            }
        }
    }

    // Normalize + write (b,s,h*64+d)
    const float inv0 = 1.f / l0, inv1 = 1.f / l1;
    const size_t row0 = (size_t)(b * SS + q0 + wid * 16 + g) * DM + h * 64;
    #pragma unroll
    for (int dt = 0; dt < 8; dt++) {
        const int col = dt * 8 + 2 * qd;
        float2 v0, v1;
        v0.x = acc[dt][0] * inv0; v0.y = acc[dt][1] * inv0;
        v1.x = acc[dt][2] * inv1; v1.y = acc[dt][3] * inv1;
        *(float2*)(g_attn + row0 + col) = v0;
        *(float2*)(g_attn + row0 + 8 * DM + col) = v1;
    }
}

extern "C" void kernel_launch(void* const* d_in, const int* in_sizes, int n_in,
                              void* d_out, int out_size)
{
    const float* x  = (const float*)d_in[0];
    const float* Qw = (const float*)d_in[1];
    const float* Qb = (const float*)d_in[2];
    const float* Kw = (const float*)d_in[3];
    const float* Kb = (const float*)d_in[4];
    const float* Vw = (const float*)d_in[5];
    const float* Vb = (const float*)d_in[6];
    const float* Ow = (const float*)d_in[7];
    const float* Ob = (const float*)d_in[8];
    float* out = (float*)d_out;

    // QKV projections fused: grid.y = 3 gemms x 8 column tiles of 128
    dim3 gq(PP / 128, 24);
    gemm_mma<<<gq, 256>>>(x, Qw, Kw, Vw, Qb, Kb, Vb, nullptr, 0);

    // Attention
    dim3 ga(SS / 64, BB * HH);
    attn_mma<<<ga, 128>>>();

    // Output projection
    dim3 go(PP / 128, DM / 128);
    gemm_mma<<<go, 256>>>(nullptr, Ow, nullptr, nullptr,
                          Ob, nullptr, nullptr, out, 1);
}

// round 10
// speedup vs baseline: 2.6207x; 1.0506x over previous
#include <cuda_runtime.h>
#include <cuda_bf16.h>
#include <cstdint>

#define BB 4
#define SS 2048
#define HH 16
#define DM 1024
#define PP (BB*SS)      // 8192 total positions

// Scratch (static device arrays -- no allocation APIs anywhere)
__device__ float g_qkv[3][PP*DM];   // q,k,v in (b,s,h*64+d) layout
__device__ float g_attn[PP*DM];     // attention output, same layout

// ---------------------------------------------------------------------------
// bf16 split helpers: x = hi + lo with hi=bf16(x), lo=bf16(x-hi).
// split2 packs a PAIR of values into one bf16x2 word (v0 -> low, v1 -> high).
// Dropping lo*lo in 3-term MMA leaves ~2^-18 relative error.
// ---------------------------------------------------------------------------
__device__ __forceinline__ void split2(float v0, float v1,
                                       uint32_t& hi, uint32_t& lo) {
    __nv_bfloat16 h0 = __float2bfloat16(v0);
    __nv_bfloat16 h1 = __float2bfloat16(v1);
    __nv_bfloat16 l0 = __float2bfloat16(v0 - __bfloat162float(h0));
    __nv_bfloat16 l1 = __float2bfloat16(v1 - __bfloat162float(h1));
    hi = (uint32_t)__bfloat16_as_ushort(h0) |
         ((uint32_t)__bfloat16_as_ushort(h1) << 16);
    lo = (uint32_t)__bfloat16_as_ushort(l0) |
         ((uint32_t)__bfloat16_as_ushort(l1) << 16);
}

// D += A * B  (m16n8k16, bf16 in, fp32 accum)
__device__ __forceinline__ void mma16(float* c, const uint32_t* a,
                                      uint32_t b0, uint32_t b1) {
    asm volatile(
        "mma.sync.aligned.m16n8k16.row.col.f32.bf16.bf16.f32 "
        "{%0,%1,%2,%3}, {%4,%5,%6,%7}, {%8,%9}, {%0,%1,%2,%3};"
        : "+f"(c[0]), "+f"(c[1]), "+f"(c[2]), "+f"(c[3])
        : "r"(a[0]), "r"(a[1]), "r"(a[2]), "r"(a[3]), "r"(b0), "r"(b1));
}

// ===========================================================================
// Projection GEMM, bf16x3. C tile 128x128, K-step 16, double-buffered.
//   mode 0 (QKV fused): A = x, B = per-(which,head) 1024x64 blocks -> g_qkv
//   mode 1 (O-proj):    A = g_attn, B = Ow (1024x1024 row-major)   -> d_out
// A smem [m][kword] pitch 12 (12*g mod 32 spans {0,12,24,4,16,28,8,20} ->
// conflict-free a-frag loads). B smem [kword][n] pitch 136 (=8 mod 32 ->
// conflict-free b-frag loads). Words are bf16x2 packed along k.
// ===========================================================================
#define APITCH 12
#define BPITCH 136

__global__ __launch_bounds__(256, 2) void gemm_bf16(
    const float* __restrict__ A,
    const float* __restrict__ W0, const float* __restrict__ W1,
    const float* __restrict__ W2,
    const float* __restrict__ B0, const float* __restrict__ B1,
    const float* __restrict__ B2,
    float* __restrict__ oout, int mode)
{
    __shared__ uint32_t Ah[2][128][APITCH], Al[2][128][APITCH];
    __shared__ uint32_t Bh[2][8][BPITCH],   Bl[2][8][BPITCH];

    const int tid  = threadIdx.x;
    const int lane = tid & 31, wid = tid >> 5;
    const int wm = wid & 1, wn = wid >> 1;        // warp grid 2(m) x 4(n)
    const int g  = lane >> 2, qd = lane & 3;
    const int p0 = blockIdx.x * 128, nt = blockIdx.y;

    const float *Ain, *W, *bias;
    float* outp;
    int cw;
    if (mode == 0) {
        const int which = nt >> 3;
        W    = (which == 0) ? W0 : (which == 1) ? W1 : W2;
        bias = (which == 0) ? B0 : (which == 1) ? B1 : B2;
        outp = g_qkv[which];
        cw = (nt & 7) * 128;
        Ain = A;
    } else {
        W = W0; bias = B0; outp = oout;
        cw = nt * 128;
        Ain = g_attn;
    }

    // per-thread producer coords
    const int ar = tid >> 2, akg = tid & 3;            // A: 2 chunks (r, r+64)
    const int bkw = tid >> 5, bn4 = tid & 31;          // B: one (kw, n4) slot
    const float* bbase;
    if (mode == 0) {
        const int c = cw + bn4 * 4;
        bbase = W + (size_t)(c >> 6) * (DM * 64) + (c & 63);
    } else {
        bbase = W + cw + bn4 * 4;
    }
    const size_t brstride = (mode == 0) ? 64 : DM;

    float4 aR[2], bRe, bRo;
    auto ldAB = [&](int k0) {
        aR[0] = *(const float4*)(Ain + (size_t)(p0 + ar) * DM + k0 + akg * 4);
        aR[1] = *(const float4*)(Ain + (size_t)(p0 + 64 + ar) * DM + k0 + akg * 4);
        const size_t r0 = (size_t)(k0 + 2 * bkw);
        bRe = *(const float4*)(bbase + r0 * brstride);
        bRo = *(const float4*)(bbase + (r0 + 1) * brstride);
    };
    auto stAB = [&](int buf) {
        #pragma unroll
        for (int q = 0; q < 2; q++) {
            const int r = q * 64 + ar;
            uint32_t h0, l0, h1, l1;
            split2(aR[q].x, aR[q].y, h0, l0);
            split2(aR[q].z, aR[q].w, h1, l1);
            *(uint2*)&Ah[buf][r][akg * 2] = make_uint2(h0, h1);
            *(uint2*)&Al[buf][r][akg * 2] = make_uint2(l0, l1);
        }
        uint32_t wh[4], wl[4];
        split2(bRe.x, bRo.x, wh[0], wl[0]);   // low half = even k row
        split2(bRe.y, bRo.y, wh[1], wl[1]);
        split2(bRe.z, bRo.z, wh[2], wl[2]);
        split2(bRe.w, bRo.w, wh[3], wl[3]);
        *(uint4*)&Bh[buf][bkw][bn4 * 4] = make_uint4(wh[0], wh[1], wh[2], wh[3]);
        *(uint4*)&Bl[buf][bkw][bn4 * 4] = make_uint4(wl[0], wl[1], wl[2], wl[3]);
    };

    float c[4][4][4] = {};

    ldAB(0);
    stAB(0);
    __syncthreads();

    for (int it = 0; it < 64; it++) {
        const int buf = it & 1;
        if (it < 63) ldAB((it + 1) * 16);

        uint32_t fa[4][4], fbh[4][2], fbl[4][2];
        #pragma unroll
        for (int mt = 0; mt < 4; mt++) {
            const int r = wm * 64 + mt * 16 + g;
            fa[mt][0] = Ah[buf][r][qd];
            fa[mt][1] = Ah[buf][r + 8][qd];
            fa[mt][2] = Ah[buf][r][qd + 4];
            fa[mt][3] = Ah[buf][r + 8][qd + 4];
        }
        #pragma unroll
        for (int nn = 0; nn < 4; nn++) {
            const int ncol = wn * 32 + nn * 8 + g;
            fbh[nn][0] = Bh[buf][qd][ncol];
            fbh[nn][1] = Bh[buf][qd + 4][ncol];
            fbl[nn][0] = Bl[buf][qd][ncol];
            fbl[nn][1] = Bl[buf][qd + 4][ncol];
        }
        #pragma unroll
        for (int mt = 0; mt < 4; mt++)
            #pragma unroll
            for (int nn = 0; nn < 4; nn++) {
                mma16(c[mt][nn], fa[mt], fbh[nn][0], fbh[nn][1]);   // hi*hi
                mma16(c[mt][nn], fa[mt], fbl[nn][0], fbl[nn][1]);   // hi*lo
            }
        #pragma unroll
        for (int mt = 0; mt < 4; mt++) {                            // reload lo
            const int r = wm * 64 + mt * 16 + g;
            fa[mt][0] = Al[buf][r][qd];
            fa[mt][1] = Al[buf][r + 8][qd];
            fa[mt][2] = Al[buf][r][qd + 4];
            fa[mt][3] = Al[buf][r + 8][qd + 4];
        }
        #pragma unroll
        for (int mt = 0; mt < 4; mt++)
            #pragma unroll
            for (int nn = 0; nn < 4; nn++)
                mma16(c[mt][nn], fa[mt], fbh[nn][0], fbh[nn][1]);   // lo*hi

        if (it < 63) stAB(buf ^ 1);
        __syncthreads();
    }

    // Epilogue: fp32 accum + bias, float2 stores
    #pragma unroll
    for (int mt = 0; mt < 4; mt++) {
        const int row = p0 + wm * 64 + mt * 16 + g;
        #pragma unroll
        for (int nn = 0; nn < 4; nn++) {
            const int col = cw + wn * 32 + nn * 8 + 2 * qd;
            const float2 bv = *(const float2*)(bias + col);
            float2 v0, v1;
            v0.x = c[mt][nn][0] + bv.x; v0.y = c[mt][nn][1] + bv.y;
            v1.x = c[mt][nn][2] + bv.x; v1.y = c[mt][nn][3] + bv.y;
            *(float2*)(outp + (size_t)row * DM + col) = v0;
            *(float2*)(outp + (size_t)(row + 8) * DM + col) = v1;
        }
    }
}

// ===========================================================================
// Flash attention, bf16x3 (m16n8k16).
// Block = (b, h, 64-q-tile), 128 thr = 4 warps; warp w owns q rows 16w..16w+15.
// Smem (pitch 72 = 8 mod 32, conflict-free frag loads):
//   Kh/Kl [dword][kpos]  (bf16x2 packed along d; also stages Q as [dword][qrow])
//   Vh/Vl [kword][d]     (bf16x2 packed along kpos)
// QK^T: Qh*Kh + Qh*Kl + Ql*Kh.  PV: Ph*Vh + Ph*Vl + Pl*Vh.
// The m16n8k16 A-fragment of PV == packed C-fragment of QK (no shfl needed).
// ===========================================================================
#define AP 72

__global__ __launch_bounds__(128) void attn_bf16()
{
    __shared__ uint32_t Kh[32][AP], Kl[32][AP];
    __shared__ uint32_t Vh[32][AP], Vl[32][AP];

    const int tid = threadIdx.x, lane = tid & 31, wid = tid >> 5;
    const int g = lane >> 2, qd = lane & 3;
    const int qt = blockIdx.x, bh = blockIdx.y;
    const int b = bh >> 4, h = bh & 15;
    const int q0 = qt * 64;
    const int lrow = tid >> 1, half = tid & 1;      // K/Q loader coords
    const int vw = tid >> 2, vdq = tid & 3;         // V loader coords

    const float* gq = g_qkv[0];
    const float* gk = g_qkv[1];
    const float* gv = g_qkv[2];

    // ---- Stage Q (pre-scaled by 1/8), packed+split, into Kh/Kl ----
    {
        const float* src = gq + (size_t)(b * SS + q0 + lrow) * DM + h * 64 + half * 32;
        #pragma unroll
        for (int j = 0; j < 8; j++) {
            float4 v = *(const float4*)(src + j * 4);
            const int dw = (half * 32 + j * 4) >> 1;
            uint32_t h0, l0, h1, l1;
            split2(v.x * 0.125f, v.y * 0.125f, h0, l0);
            split2(v.z * 0.125f, v.w * 0.125f, h1, l1);
            Kh[dw][lrow] = h0; Kh[dw + 1][lrow] = h1;
            Kl[dw][lrow] = l0; Kl[dw + 1][lrow] = l1;
        }
    }
    __syncthreads();

    // ---- Q fragments (hi & lo), resident for the whole block ----
    uint32_t qh[4][4], ql[4][4];
    {
        const int r = wid * 16 + g;
        #pragma unroll
        for (int t = 0; t < 4; t++) {
            qh[t][0] = Kh[t * 8 + qd][r];     qh[t][1] = Kh[t * 8 + qd][r + 8];
            qh[t][2] = Kh[t * 8 + qd + 4][r]; qh[t][3] = Kh[t * 8 + qd + 4][r + 8];
            ql[t][0] = Kl[t * 8 + qd][r];     ql[t][1] = Kl[t * 8 + qd][r + 8];
            ql[t][2] = Kl[t * 8 + qd + 4][r]; ql[t][3] = Kl[t * 8 + qd + 4][r + 8];
        }
    }

    float m0 = -1e30f, m1 = -1e30f, l0s = 0.f, l1s = 0.f;
    float acc[8][4] = {};

    for (int kt = 0; kt <= qt; kt++) {
        __syncthreads();   // staging/frag reads (or previous tile) complete
        const int k0 = kt * 64;
        // ---- K tile: packed along d ----
        {
            const float* ks = gk + (size_t)(b * SS + k0 + lrow) * DM + h * 64 + half * 32;
            #pragma unroll
            for (int j = 0; j < 8; j++) {
                float4 v = *(const float4*)(ks + j * 4);
                const int dw = (half * 32 + j * 4) >> 1;
                uint32_t h0, lo0, h1, lo1;
                split2(v.x, v.y, h0, lo0);
                split2(v.z, v.w, h1, lo1);
                Kh[dw][lrow] = h0; Kh[dw + 1][lrow] = h1;
                Kl[dw][lrow] = lo0; Kl[dw + 1][lrow] = lo1;
            }
        }
        // ---- V tile: packed along kpos (rows 2vw, 2vw+1) ----
        {
            const float* v0p = gv + (size_t)(b * SS + k0 + 2 * vw) * DM + h * 64 + vdq * 16;
            const float* v1p = v0p + DM;
            #pragma unroll
            for (int i = 0; i < 4; i++) {
                float4 va = *(const float4*)(v0p + i * 4);
                float4 vb = *(const float4*)(v1p + i * 4);
                uint32_t hh[4], ll[4];
                split2(va.x, vb.x, hh[0], ll[0]);
                split2(va.y, vb.y, hh[1], ll[1]);
                split2(va.z, vb.z, hh[2], ll[2]);
                split2(va.w, vb.w, hh[3], ll[3]);
                *(uint4*)&Vh[vw][vdq * 16 + i * 4] = make_uint4(hh[0], hh[1], hh[2], hh[3]);
                *(uint4*)&Vl[vw][vdq * 16 + i * 4] = make_uint4(ll[0], ll[1], ll[2], ll[3]);
            }
        }
        __syncthreads();

        // ---- S = (Q/8) K^T, 3-term ----
        float c[8][4] = {};
        #pragma unroll
        for (int nt = 0; nt < 8; nt++) {
            #pragma unroll
            for (int t = 0; t < 4; t++) {
                const int kc = nt * 8 + g;
                uint32_t bh0 = Kh[t * 8 + qd][kc], bh1 = Kh[t * 8 + qd + 4][kc];
                uint32_t bl0 = Kl[t * 8 + qd][kc], bl1 = Kl[t * 8 + qd + 4][kc];
                mma16(c[nt], qh[t], bh0, bh1);
                mma16(c[nt], qh[t], bl0, bl1);
                mma16(c[nt], ql[t], bh0, bh1);
            }
        }

        // ---- causal mask (diagonal tile only) ----
        if (kt == qt) {
            const int qg0 = q0 + wid * 16 + g, qg1 = qg0 + 8;
            #pragma unroll
            for (int nt = 0; nt < 8; nt++) {
                const int c0 = k0 + nt * 8 + 2 * qd;
                if (c0     > qg0) c[nt][0] = -100000.f;
                if (c0 + 1 > qg0) c[nt][1] = -100000.f;
                if (c0     > qg1) c[nt][2] = -100000.f;
                if (c0 + 1 > qg1) c[nt][3] = -100000.f;
            }
        }

        // ---- online softmax (rows g, g+8; quad spans 64 cols) ----
        float rmax0 = -1e30f, rmax1 = -1e30f;
        #pragma unroll
        for (int nt = 0; nt < 8; nt++) {
            rmax0 = fmaxf(rmax0, fmaxf(c[nt][0], c[nt][1]));
            rmax1 = fmaxf(rmax1, fmaxf(c[nt][2], c[nt][3]));
        }
        rmax0 = fmaxf(rmax0, __shfl_xor_sync(0xffffffffu, rmax0, 1));
        rmax0 = fmaxf(rmax0, __shfl_xor_sync(0xffffffffu, rmax0, 2));
        rmax1 = fmaxf(rmax1, __shfl_xor_sync(0xffffffffu, rmax1, 1));
        rmax1 = fmaxf(rmax1, __shfl_xor_sync(0xffffffffu, rmax1, 2));

        const float nm0 = fmaxf(m0, rmax0), nm1 = fmaxf(m1, rmax1);
        const float f0 = __expf(m0 - nm0), f1 = __expf(m1 - nm1);
        float s0 = 0.f, s1 = 0.f;
        #pragma unroll
        for (int nt = 0; nt < 8; nt++) {
            c[nt][0] = __expf(c[nt][0] - nm0); s0 += c[nt][0];
            c[nt][1] = __expf(c[nt][1] - nm0); s0 += c[nt][1];
            c[nt][2] = __expf(c[nt][2] - nm1); s1 += c[nt][2];
            c[nt][3] = __expf(c[nt][3] - nm1); s1 += c[nt][3];
        }
        s0 += __shfl_xor_sync(0xffffffffu, s0, 1);
        s0 += __shfl_xor_sync(0xffffffffu, s0, 2);
        s1 += __shfl_xor_sync(0xffffffffu, s1, 1);
        s1 += __shfl_xor_sync(0xffffffffu, s1, 2);
        l0s = l0s * f0 + s0; l1s = l1s * f1 + s1;
        m0 = nm0; m1 = nm1;
        #pragma unroll
        for (int dt = 0; dt < 8; dt++) {
            acc[dt][0] *= f0; acc[dt][1] *= f0;
            acc[dt][2] *= f1; acc[dt][3] *= f1;
        }

        // ---- PV, 3-term; A-frag = packed C-frag (no shfl) ----
        #pragma unroll
        for (int t = 0; t < 4; t++) {
            uint32_t ah[4], al[4];
            split2(c[2 * t][0],     c[2 * t][1],     ah[0], al[0]);
            split2(c[2 * t][2],     c[2 * t][3],     ah[1], al[1]);
            split2(c[2 * t + 1][0], c[2 * t + 1][1], ah[2], al[2]);
            split2(c[2 * t + 1][2], c[2 * t + 1][3], ah[3], al[3]);
            #pragma unroll
            for (int dt = 0; dt < 8; dt++) {
                const int dc = dt * 8 + g;
                uint32_t bh0 = Vh[t * 8 + qd][dc], bh1 = Vh[t * 8 + qd + 4][dc];
                uint32_t bl0 = Vl[t * 8 + qd][dc], bl1 = Vl[t * 8 + qd + 4][dc];
                mma16(acc[dt], ah, bh0, bh1);
                mma16(acc[dt], ah, bl0, bl1);
                mma16(acc[dt], al, bh0, bh1);
            }
        }
    }

    // ---- normalize + write (b,s,h*64+d) ----
    const float inv0 = 1.f / l0s, inv1 = 1.f / l1s;
    const size_t row0 = (size_t)(b * SS + q0 + wid * 16 + g) * DM + h * 64;
    #pragma unroll
    for (int dt = 0; dt < 8; dt++) {
        const int col = dt * 8 + 2 * qd;
        float2 v0, v1;
        v0.x = acc[dt][0] * inv0; v0.y = acc[dt][1] * inv0;
        v1.x = acc[dt][2] * inv1; v1.y = acc[dt][3] * inv1;
        *(float2*)(g_attn + row0 + col) = v0;
        *(float2*)(g_attn + row0 + 8 * DM + col) = v1;
    }
}

extern "C" void kernel_launch(void* const* d_in, const int* in_sizes, int n_in,
                              void* d_out, int out_size)
{
    const float* x  = (const float*)d_in[0];
    const float* Qw = (const float*)d_in[1];
    const float* Qb = (const float*)d_in[2];
    const float* Kw = (const float*)d_in[3];
    const float* Kb = (const float*)d_in[4];
    const float* Vw = (const float*)d_in[5];
    const float* Vb = (const float*)d_in[6];
    const float* Ow = (const float*)d_in[7];
    const float* Ob = (const float*)d_in[8];
    float* out = (float*)d_out;

    // QKV projections fused: grid.y = 3 gemms x 8 column tiles of 128
    dim3 gq(PP / 128, 24);
    gemm_bf16<<<gq, 256>>>(x, Qw, Kw, Vw, Qb, Kb, Vb, nullptr, 0);

    // Attention
    dim3 ga(SS / 64, BB * HH);
    attn_bf16<<<ga, 128>>>();

    // Output projection
    dim3 go(PP / 128, DM / 128);
    gemm_bf16<<<go, 256>>>(nullptr, Ow, nullptr, nullptr,
                           Ob, nullptr, nullptr, out, 1);
}

// round 11
// speedup vs baseline: 2.7306x; 1.0419x over previous
#include <cuda_runtime.h>
#include <cuda_bf16.h>
#include <cstdint>

#define BB 4
#define SS 2048
#define HH 16
#define DM 1024
#define PP (BB*SS)      // 8192 total positions
#define NW (DM/2)       // 512 bf16x2 words per row

// ---------------------------------------------------------------------------
// Scratch: everything stored as bf16 hi/lo word pairs (packed along k-dim)
// ---------------------------------------------------------------------------
__device__ uint32_t g_xh[PP*NW],  g_xl[PP*NW];          // x split
__device__ uint32_t g_wph[4][NW*DM], g_wpl[4][NW*DM];   // weights [kw][n] packed
__device__ uint32_t g_qh[3][PP*NW], g_ql[3][PP*NW];     // q(k-scaled),k,v split
__device__ uint32_t g_ah[PP*NW],  g_al[PP*NW];          // attention out split

// ---------------------------------------------------------------------------
// helpers
// ---------------------------------------------------------------------------
__device__ __forceinline__ void split2(float v0, float v1,
                                       uint32_t& hi, uint32_t& lo) {
    __nv_bfloat16 h0 = __float2bfloat16(v0);
    __nv_bfloat16 h1 = __float2bfloat16(v1);
    __nv_bfloat16 l0 = __float2bfloat16(v0 - __bfloat162float(h0));
    __nv_bfloat16 l1 = __float2bfloat16(v1 - __bfloat162float(h1));
    hi = (uint32_t)__bfloat16_as_ushort(h0) |
         ((uint32_t)__bfloat16_as_ushort(h1) << 16);
    lo = (uint32_t)__bfloat16_as_ushort(l0) |
         ((uint32_t)__bfloat16_as_ushort(l1) << 16);
}

__device__ __forceinline__ uint32_t prmt(uint32_t a, uint32_t b, uint32_t s) {
    uint32_t r;
    asm("prmt.b32 %0, %1, %2, %3;" : "=r"(r) : "r"(a), "r"(b), "r"(s));
    return r;
}

// D += A * B  (m16n8k16, bf16 in, fp32 accum)
__device__ __forceinline__ void mma16(float* c, const uint32_t* a,
                                      uint32_t b0, uint32_t b1) {
    asm volatile(
        "mma.sync.aligned.m16n8k16.row.col.f32.bf16.bf16.f32 "
        "{%0,%1,%2,%3}, {%4,%5,%6,%7}, {%8,%9}, {%0,%1,%2,%3};"
        : "+f"(c[0]), "+f"(c[1]), "+f"(c[2]), "+f"(c[3])
        : "r"(a[0]), "r"(a[1]), "r"(a[2]), "r"(a[3]), "r"(b0), "r"(b1));
}

// ---------------------------------------------------------------------------
// Prep: split x, and split+transpose weights into [kw][n] packed-pair layout
// ---------------------------------------------------------------------------
__global__ __launch_bounds__(256) void prep_x(const float* __restrict__ x) {
    const size_t i = (size_t)blockIdx.x * 256 + threadIdx.x;   // over PP*NW
    float2 v = *(const float2*)(x + 2 * i);
    split2(v.x, v.y, g_xh[i], g_xl[i]);
}

__global__ __launch_bounds__(256) void prep_w(
    const float* __restrict__ Qw, const float* __restrict__ Kw,
    const float* __restrict__ Vw, const float* __restrict__ Ow) {
    const int i = blockIdx.x * 256 + threadIdx.x;   // over 4 * NW*DM (2^21)
    const int which = i >> 19;                       // NW*DM = 2^19
    const int rem = i & ((NW * DM) - 1);
    const int kw = rem >> 10, n = rem & 1023;
    float v0, v1;
    if (which < 3) {
        const float* W = (which == 0) ? Qw : (which == 1) ? Kw : Vw;
        const int h = n >> 6, d = n & 63;
        const float* p = W + ((size_t)h * DM + 2 * kw) * 64 + d;
        v0 = p[0]; v1 = p[64];
    } else {
        const float* p = Ow + (size_t)(2 * kw) * DM + n;
        v0 = p[0]; v1 = p[DM];
    }
    split2(v0, v1, ((uint32_t*)g_wph)[i], ((uint32_t*)g_wpl)[i]);
}

// ===========================================================================
// GEMM bf16x3, zero in-loop conversion. C tile 128x128, k-step 16, dbl-buffer.
//   mode 0 (QKV): A = g_xh/xl, B = g_wp[which] -> g_qh/ql[which] (Q scaled 1/8)
//   mode 1 (O):   A = g_ah/al, B = g_wp[3]     -> fp32 d_out + bias
// A smem [m][kw] pitch 12 (conflict-free consumer), B smem [kw][n] pitch 136.
// ===========================================================================
#define APITCH 12
#define BPITCH 136

__global__ __launch_bounds__(256, 2) void gemm_bf16(
    const float* __restrict__ B0, const float* __restrict__ B1,
    const float* __restrict__ B2,
    float* __restrict__ oout, int mode)
{
    __shared__ uint32_t Ah[2][128][APITCH], Al[2][128][APITCH];
    __shared__ uint32_t Bh[2][8][BPITCH],   Bl[2][8][BPITCH];

    const int tid  = threadIdx.x;
    const int lane = tid & 31, wid = tid >> 5;
    const int wm = wid & 1, wn = wid >> 1;        // warp grid 2(m) x 4(n)
    const int g  = lane >> 2, qd = lane & 3;
    const int p0 = blockIdx.x * 128, nt = blockIdx.y;

    const int which = (mode == 0) ? (nt >> 3) : 3;
    const int cw    = (mode == 0) ? (nt & 7) * 128 : nt * 128;
    const float* bias = (mode == 0)
        ? ((which == 0) ? B0 : (which == 1) ? B1 : B2) : B0;
    const uint32_t* Awh = (mode == 0) ? g_xh : g_ah;
    const uint32_t* Awl = (mode == 0) ? g_xl : g_al;
    const uint32_t* wph = g_wph[which];
    const uint32_t* wpl = g_wpl[which];

    // producer coords: A 128 rows x 2 half-rows; B 8 kw x 32 n-quads
    const int ar = tid >> 1, ah4 = (tid & 1) * 4;
    const int bkw = tid >> 5, bn4 = (tid & 31) * 4;

    uint4 ra_h, ra_l, rb_h, rb_l;
    auto ldAB = [&](int it) {
        const size_t aw = (size_t)(p0 + ar) * NW + it * 8 + ah4;
        ra_h = *(const uint4*)(Awh + aw);
        ra_l = *(const uint4*)(Awl + aw);
        const size_t bw = (size_t)(it * 8 + bkw) * DM + cw + bn4;
        rb_h = *(const uint4*)(wph + bw);
        rb_l = *(const uint4*)(wpl + bw);
    };
    auto stAB = [&](int buf) {
        *(uint4*)&Ah[buf][ar][ah4] = ra_h;
        *(uint4*)&Al[buf][ar][ah4] = ra_l;
        *(uint4*)&Bh[buf][bkw][bn4] = rb_h;
        *(uint4*)&Bl[buf][bkw][bn4] = rb_l;
    };

    float c[4][4][4] = {};

    ldAB(0);
    stAB(0);
    __syncthreads();

    for (int it = 0; it < 64; it++) {
        const int buf = it & 1;
        if (it < 63) ldAB(it + 1);

        uint32_t fa[4][4], fbh[4][2], fbl[4][2];
        #pragma unroll
        for (int mt = 0; mt < 4; mt++) {
            const int r = wm * 64 + mt * 16 + g;
            fa[mt][0] = Ah[buf][r][qd];
            fa[mt][1] = Ah[buf][r + 8][qd];
            fa[mt][2] = Ah[buf][r][qd + 4];
            fa[mt][3] = Ah[buf][r + 8][qd + 4];
        }
        #pragma unroll
        for (int nn = 0; nn < 4; nn++) {
            const int ncol = wn * 32 + nn * 8 + g;
            fbh[nn][0] = Bh[buf][qd][ncol];
            fbh[nn][1] = Bh[buf][qd + 4][ncol];
            fbl[nn][0] = Bl[buf][qd][ncol];
            fbl[nn][1] = Bl[buf][qd + 4][ncol];
        }
        #pragma unroll
        for (int mt = 0; mt < 4; mt++)
            #pragma unroll
            for (int nn = 0; nn < 4; nn++) {
                mma16(c[mt][nn], fa[mt], fbh[nn][0], fbh[nn][1]);   // hi*hi
                mma16(c[mt][nn], fa[mt], fbl[nn][0], fbl[nn][1]);   // hi*lo
            }
        #pragma unroll
        for (int mt = 0; mt < 4; mt++) {                            // lo frags
            const int r = wm * 64 + mt * 16 + g;
            fa[mt][0] = Al[buf][r][qd];
            fa[mt][1] = Al[buf][r + 8][qd];
            fa[mt][2] = Al[buf][r][qd + 4];
            fa[mt][3] = Al[buf][r + 8][qd + 4];
        }
        #pragma unroll
        for (int mt = 0; mt < 4; mt++)
            #pragma unroll
            for (int nn = 0; nn < 4; nn++)
                mma16(c[mt][nn], fa[mt], fbh[nn][0], fbh[nn][1]);   // lo*hi

        if (it < 63) stAB(buf ^ 1);
        __syncthreads();
    }

    // Epilogue
    if (mode == 1) {
        #pragma unroll
        for (int mt = 0; mt < 4; mt++) {
            const int row = p0 + wm * 64 + mt * 16 + g;
            #pragma unroll
            for (int nn = 0; nn < 4; nn++) {
                const int col = cw + wn * 32 + nn * 8 + 2 * qd;
                const float2 bv = *(const float2*)(bias + col);
                float2 v0, v1;
                v0.x = c[mt][nn][0] + bv.x; v0.y = c[mt][nn][1] + bv.y;
                v1.x = c[mt][nn][2] + bv.x; v1.y = c[mt][nn][3] + bv.y;
                *(float2*)(oout + (size_t)row * DM + col) = v0;
                *(float2*)(oout + (size_t)(row + 8) * DM + col) = v1;
            }
        }
    } else {
        const float sc = (which == 0) ? 0.125f : 1.0f;   // fold 1/sqrt(64) into Q
        uint32_t* oh = g_qh[which];
        uint32_t* ol = g_ql[which];
        #pragma unroll
        for (int mt = 0; mt < 4; mt++) {
            const int row = p0 + wm * 64 + mt * 16 + g;
            #pragma unroll
            for (int nn = 0; nn < 4; nn++) {
                const int col = cw + wn * 32 + nn * 8 + 2 * qd;
                const float2 bv = *(const float2*)(bias + col);
                const size_t w0 = (size_t)row * NW + (col >> 1);
                const size_t w1 = (size_t)(row + 8) * NW + (col >> 1);
                split2((c[mt][nn][0] + bv.x) * sc, (c[mt][nn][1] + bv.y) * sc,
                       oh[w0], ol[w0]);
                split2((c[mt][nn][2] + bv.x) * sc, (c[mt][nn][3] + bv.y) * sc,
                       oh[w1], ol[w1]);
            }
        }
    }
}

// ===========================================================================
// Flash attention bf16x3, q-tile 128, 256 threads (8 warps x 16 q-rows).
// Zero-conversion loads (data pre-split). Q fragments straight from global.
// K smem [kpos][dword] pitch 36 (conflict-free everywhere).
// V smem [kword][d]    pitch 72, packed along kpos via PRMT.
// QK: Qh*Kh + Qh*Kl + Ql*Kh.  PV: Ph*Vh + Ph*Vl + Pl*Vh (P split in-register).
// ===========================================================================
#define KPP 36
#define VPP 72

__global__ __launch_bounds__(256) void attn_bf16()
{
    __shared__ uint32_t Kh[64][KPP], Kl[64][KPP];
    __shared__ uint32_t Vh[32][VPP], Vl[32][VPP];

    const int tid = threadIdx.x, lane = tid & 31, w = tid >> 5;
    const int g = lane >> 2, qd = lane & 3;
    const int qt = blockIdx.x, bh = blockIdx.y;
    const int b = bh >> 4, h = bh & 15;
    const int q0 = qt * 128;
    const int kr = tid >> 2, kdq = (tid & 3) * 8;   // K loader
    const int vw = tid >> 3, vg = tid & 7;          // V loader

    // ---- Q fragments (hi & lo) straight from global, resident all block ----
    uint32_t qh[4][4], ql[4][4];
    {
        const size_t rw = (size_t)(b * SS + q0 + w * 16 + g) * NW + h * 32;
        const uint32_t* ph = g_qh[0] + rw;
        const uint32_t* pl = g_ql[0] + rw;
        #pragma unroll
        for (int t = 0; t < 4; t++) {
            qh[t][0] = ph[t * 8 + qd];          qh[t][1] = ph[8 * NW + t * 8 + qd];
            qh[t][2] = ph[t * 8 + qd + 4];      qh[t][3] = ph[8 * NW + t * 8 + qd + 4];
            ql[t][0] = pl[t * 8 + qd];          ql[t][1] = pl[8 * NW + t * 8 + qd];
            ql[t][2] = pl[t * 8 + qd + 4];      ql[t][3] = pl[8 * NW + t * 8 + qd + 4];
        }
    }

    float m0 = -1e30f, m1 = -1e30f, l0s = 0.f, l1s = 0.f;
    float acc[8][4] = {};

    const int nkt = 2 * qt + 2;
    for (int kt = 0; kt < nkt; kt++) {
        __syncthreads();   // previous tile's smem reads complete
        const int k0 = kt * 64;

        // ---- K tile: straight copy, [kpos][dword] ----
        {
            const size_t rw = (size_t)(b * SS + k0 + kr) * NW + h * 32 + kdq;
            *(uint4*)&Kh[kr][kdq]     = *(const uint4*)(g_qh[1] + rw);
            *(uint4*)&Kh[kr][kdq + 4] = *(const uint4*)(g_qh[1] + rw + 4);
            *(uint4*)&Kl[kr][kdq]     = *(const uint4*)(g_ql[1] + rw);
            *(uint4*)&Kl[kr][kdq + 4] = *(const uint4*)(g_ql[1] + rw + 4);
        }
        // ---- V tile: interleave rows 2vw, 2vw+1 along kpos via PRMT ----
        {
            const size_t rw = (size_t)(b * SS + k0 + 2 * vw) * NW + h * 32 + vg * 4;
            uint4 eh = *(const uint4*)(g_qh[2] + rw);
            uint4 ohr = *(const uint4*)(g_qh[2] + rw + NW);
            uint4 s0, s1;
            s0.x = prmt(eh.x, ohr.x, 0x5410); s0.y = prmt(eh.x, ohr.x, 0x7632);
            s0.z = prmt(eh.y, ohr.y, 0x5410); s0.w = prmt(eh.y, ohr.y, 0x7632);
            s1.x = prmt(eh.z, ohr.z, 0x5410); s1.y = prmt(eh.z, ohr.z, 0x7632);
            s1.z = prmt(eh.w, ohr.w, 0x5410); s1.w = prmt(eh.w, ohr.w, 0x7632);
            *(uint4*)&Vh[vw][vg * 8]     = s0;
            *(uint4*)&Vh[vw][vg * 8 + 4] = s1;
            uint4 el = *(const uint4*)(g_ql[2] + rw);
            uint4 olr = *(const uint4*)(g_ql[2] + rw + NW);
            s0.x = prmt(el.x, olr.x, 0x5410); s0.y = prmt(el.x, olr.x, 0x7632);
            s0.z = prmt(el.y, olr.y, 0x5410); s0.w = prmt(el.y, olr.y, 0x7632);
            s1.x = prmt(el.z, olr.z, 0x5410); s1.y = prmt(el.z, olr.z, 0x7632);
            s1.z = prmt(el.w, olr.w, 0x5410); s1.w = prmt(el.w, olr.w, 0x7632);
            *(uint4*)&Vl[vw][vg * 8]     = s0;
            *(uint4*)&Vl[vw][vg * 8 + 4] = s1;
        }
        __syncthreads();

        if (k0 > q0 + w * 16 + 15) continue;   // fully-masked for this warp

        // ---- S = Q K^T (Q pre-scaled), 3-term ----
        float c[8][4] = {};
        #pragma unroll
        for (int nt = 0; nt < 8; nt++) {
            #pragma unroll
            for (int t = 0; t < 4; t++) {
                const int kc = nt * 8 + g;
                uint32_t bh0 = Kh[kc][t * 8 + qd], bh1 = Kh[kc][t * 8 + qd + 4];
                uint32_t bl0 = Kl[kc][t * 8 + qd], bl1 = Kl[kc][t * 8 + qd + 4];
                mma16(c[nt], qh[t], bh0, bh1);
                mma16(c[nt], qh[t], bl0, bl1);
                mma16(c[nt], ql[t], bh0, bh1);
            }
        }

        // ---- causal mask (tiles overlapping this warp's diagonal) ----
        if (k0 + 63 > q0 + w * 16) {
            const int qg0 = q0 + w * 16 + g, qg1 = qg0 + 8;
            #pragma unroll
            for (int nt = 0; nt < 8; nt++) {
                const int c0 = k0 + nt * 8 + 2 * qd;
                if (c0     > qg0) c[nt][0] = -100000.f;
                if (c0 + 1 > qg0) c[nt][1] = -100000.f;
                if (c0     > qg1) c[nt][2] = -100000.f;
                if (c0 + 1 > qg1) c[nt][3] = -100000.f;
            }
        }

        // ---- online softmax (rows g, g+8) ----
        float rmax0 = -1e30f, rmax1 = -1e30f;
        #pragma unroll
        for (int nt = 0; nt < 8; nt++) {
            rmax0 = fmaxf(rmax0, fmaxf(c[nt][0], c[nt][1]));
            rmax1 = fmaxf(rmax1, fmaxf(c[nt][2], c[nt][3]));
        }
        rmax0 = fmaxf(rmax0, __shfl_xor_sync(0xffffffffu, rmax0, 1));
        rmax0 = fmaxf(rmax0, __shfl_xor_sync(0xffffffffu, rmax0, 2));
        rmax1 = fmaxf(rmax1, __shfl_xor_sync(0xffffffffu, rmax1, 1));
        rmax1 = fmaxf(rmax1, __shfl_xor_sync(0xffffffffu, rmax1, 2));

        const float nm0 = fmaxf(m0, rmax0), nm1 = fmaxf(m1, rmax1);
        const float f0 = __expf(m0 - nm0), f1 = __expf(m1 - nm1);
        float s0 = 0.f, s1 = 0.f;
        #pragma unroll
        for (int nt = 0; nt < 8; nt++) {
            c[nt][0] = __expf(c[nt][0] - nm0); s0 += c[nt][0];
            c[nt][1] = __expf(c[nt][1] - nm0); s0 += c[nt][1];
            c[nt][2] = __expf(c[nt][2] - nm1); s1 += c[nt][2];
            c[nt][3] = __expf(c[nt][3] - nm1); s1 += c[nt][3];
        }
        s0 += __shfl_xor_sync(0xffffffffu, s0, 1);
        s0 += __shfl_xor_sync(0xffffffffu, s0, 2);
        s1 += __shfl_xor_sync(0xffffffffu, s1, 1);
        s1 += __shfl_xor_sync(0xffffffffu, s1, 2);
        l0s = l0s * f0 + s0; l1s = l1s * f1 + s1;
        m0 = nm0; m1 = nm1;
        #pragma unroll
        for (int dt = 0; dt < 8; dt++) {
            acc[dt][0] *= f0; acc[dt][1] *= f0;
            acc[dt][2] *= f1; acc[dt][3] *= f1;
        }

        // ---- PV, 3-term; A-frag = packed C-frag ----
        #pragma unroll
        for (int t = 0; t < 4; t++) {
            uint32_t ah[4], al[4];
            split2(c[2 * t][0],     c[2 * t][1],     ah[0], al[0]);
            split2(c[2 * t][2],     c[2 * t][3],     ah[1], al[1]);
            split2(c[2 * t + 1][0], c[2 * t + 1][1], ah[2], al[2]);
            split2(c[2 * t + 1][2], c[2 * t + 1][3], ah[3], al[3]);
            #pragma unroll
            for (int dt = 0; dt < 8; dt++) {
                const int dc = dt * 8 + g;
                uint32_t bh0 = Vh[t * 8 + qd][dc], bh1 = Vh[t * 8 + qd + 4][dc];
                uint32_t bl0 = Vl[t * 8 + qd][dc], bl1 = Vl[t * 8 + qd + 4][dc];
                mma16(acc[dt], ah, bh0, bh1);
                mma16(acc[dt], ah, bl0, bl1);
                mma16(acc[dt], al, bh0, bh1);
            }
        }
    }

    // ---- normalize + write split hi/lo (O-proj consumes these directly) ----
    const float inv0 = 1.f / l0s, inv1 = 1.f / l1s;
    const size_t r0w = (size_t)(b * SS + q0 + w * 16 + g) * NW + h * 32;
    #pragma unroll
    for (int dt = 0; dt < 8; dt++) {
        const size_t w0 = r0w + dt * 4 + qd;
        const size_t w1 = w0 + 8 * NW;
        split2(acc[dt][0] * inv0, acc[dt][1] * inv0, g_ah[w0], g_al[w0]);
        split2(acc[dt][2] * inv1, acc[dt][3] * inv1, g_ah[w1], g_al[w1]);
    }
}

extern "C" void kernel_launch(void* const* d_in, const int* in_sizes, int n_in,
                              void* d_out, int out_size)
{
    const float* x  = (const float*)d_in[0];
    const float* Qw = (const float*)d_in[1];
    const float* Qb = (const float*)d_in[2];
    const float* Kw = (const float*)d_in[3];
    const float* Kb = (const float*)d_in[4];
    const float* Vw = (const float*)d_in[5];
    const float* Vb = (const float*)d_in[6];
    const float* Ow = (const float*)d_in[7];
    const float* Ob = (const float*)d_in[8];
    float* out = (float*)d_out;

    // One-time splits (memory-bound, ~tens of us)
    prep_x<<<(PP * NW) / 256, 256>>>(x);
    prep_w<<<(4 * NW * DM) / 256, 256>>>(Qw, Kw, Vw, Ow);

    // QKV projections fused: grid.y = 3 gemms x 8 column tiles of 128
    dim3 gq(PP / 128, 24);
    gemm_bf16<<<gq, 256>>>(Qb, Kb, Vb, nullptr, 0);

    // Attention (q-tile 128)
    dim3 ga(SS / 128, BB * HH);
    attn_bf16<<<ga, 256>>>();

    // Output projection
    dim3 go(PP / 128, DM / 128);
    gemm_bf16<<<go, 256>>>(Ob, nullptr, nullptr, out, 1);
}

// round 13
// speedup vs baseline: 2.9785x; 1.0908x over previous
#include <cuda_runtime.h>
#include <cuda_bf16.h>
#include <cstdint>

#define BB 4
#define SS 2048
#define HH 16
#define DM 1024
#define PP (BB*SS)      // 8192 total positions
#define NW (DM/2)       // 512 bf16x2 words per row

// ---------------------------------------------------------------------------
// Scratch: bf16 hi/lo word pairs. q/k packed along d; v packed along kpos.
// ---------------------------------------------------------------------------
__device__ uint32_t g_xh[PP*NW],  g_xl[PP*NW];          // x split
__device__ uint32_t g_wph[4][NW*DM], g_wpl[4][NW*DM];   // weights [kw][n]
__device__ uint32_t g_qh[2][PP*NW], g_ql[2][PP*NW];     // q(scaled), k
__device__ uint32_t g_vh[(PP/2)*DM], g_vl[(PP/2)*DM];   // v [pos-pair][h*64+d]
__device__ uint32_t g_ah[PP*NW],  g_al[PP*NW];          // attention out

// ---------------------------------------------------------------------------
// helpers
// ---------------------------------------------------------------------------
__device__ __forceinline__ void split2(float v0, float v1,
                                       uint32_t& hi, uint32_t& lo) {
    __nv_bfloat16 h0 = __float2bfloat16(v0);
    __nv_bfloat16 h1 = __float2bfloat16(v1);
    __nv_bfloat16 l0 = __float2bfloat16(v0 - __bfloat162float(h0));
    __nv_bfloat16 l1 = __float2bfloat16(v1 - __bfloat162float(h1));
    hi = (uint32_t)__bfloat16_as_ushort(h0) |
         ((uint32_t)__bfloat16_as_ushort(h1) << 16);
    lo = (uint32_t)__bfloat16_as_ushort(l0) |
         ((uint32_t)__bfloat16_as_ushort(l1) << 16);
}

__device__ __forceinline__ uint32_t smem_u32(const void* p) {
    uint32_t a;
    asm("{ .reg .u64 t; cvta.to.shared.u64 t, %1; cvt.u32.u64 %0, t; }"
        : "=r"(a) : "l"(p));
    return a;
}
__device__ __forceinline__ void cpa(uint32_t dst, const void* src) {
    asm volatile("cp.async.cg.shared.global [%0], [%1], 16;"
                 :: "r"(dst), "l"(src));
}
#define CP_COMMIT() asm volatile("cp.async.commit_group;" ::: "memory")
#define CP_WAIT1()  asm volatile("cp.async.wait_group 1;" ::: "memory")
#define CP_WAIT0()  asm volatile("cp.async.wait_group 0;" ::: "memory")

// D += A * B  (m16n8k16, bf16 in, fp32 accum)
__device__ __forceinline__ void mma16(float* c, const uint32_t* a,
                                      uint32_t b0, uint32_t b1) {
    asm volatile(
        "mma.sync.aligned.m16n8k16.row.col.f32.bf16.bf16.f32 "
        "{%0,%1,%2,%3}, {%4,%5,%6,%7}, {%8,%9}, {%0,%1,%2,%3};"
        : "+f"(c[0]), "+f"(c[1]), "+f"(c[2]), "+f"(c[3])
        : "r"(a[0]), "r"(a[1]), "r"(a[2]), "r"(a[3]), "r"(b0), "r"(b1));
}

// ---------------------------------------------------------------------------
// Prep: split x; split+transpose weights into [kw][n] packed layout
// ---------------------------------------------------------------------------
__global__ __launch_bounds__(256) void prep_x(const float* __restrict__ x) {
    const size_t i = (size_t)blockIdx.x * 256 + threadIdx.x;
    float2 v = *(const float2*)(x + 2 * i);
    split2(v.x, v.y, g_xh[i], g_xl[i]);
}

__global__ __launch_bounds__(256) void prep_w(
    const float* __restrict__ Qw, const float* __restrict__ Kw,
    const float* __restrict__ Vw, const float* __restrict__ Ow) {
    const int i = blockIdx.x * 256 + threadIdx.x;
    const int which = i >> 19;                       // NW*DM = 2^19
    const int rem = i & ((NW * DM) - 1);
    const int kw = rem >> 10, n = rem & 1023;
    float v0, v1;
    if (which < 3) {
        const float* W = (which == 0) ? Qw : (which == 1) ? Kw : Vw;
        const int h = n >> 6, d = n & 63;
        const float* p = W + ((size_t)h * DM + 2 * kw) * 64 + d;
        v0 = p[0]; v1 = p[64];
    } else {
        const float* p = Ow + (size_t)(2 * kw) * DM + n;
        v0 = p[0]; v1 = p[DM];
    }
    split2(v0, v1, ((uint32_t*)g_wph)[i], ((uint32_t*)g_wpl)[i]);
}

// ===========================================================================
// GEMM bf16x3, cp.async double-buffered. C tile 128x128, k-step 16.
//   mode 0 (QKV): A = g_xh/xl, B = g_wp[which]
//       which 0 -> g_qh/ql[0] (scaled 1/8); 1 -> g_qh/ql[1]; 2 -> g_vh/vl pack
//   mode 1 (O):   A = g_ah/al, B = g_wp[3] -> fp32 d_out + bias
// ===========================================================================
#define APITCH 12
#define BPITCH 136

__global__ __launch_bounds__(256, 2) void gemm_bf16(
    const float* __restrict__ B0, const float* __restrict__ B1,
    const float* __restrict__ B2,
    float* __restrict__ oout, int mode)
{
    __shared__ __align__(16) uint32_t Ah[2][128][APITCH], Al[2][128][APITCH];
    __shared__ __align__(16) uint32_t Bh[2][8][BPITCH],   Bl[2][8][BPITCH];

    const int tid  = threadIdx.x;
    const int lane = tid & 31, wid = tid >> 5;
    const int wm = wid & 1, wn = wid >> 1;
    const int g  = lane >> 2, qd = lane & 3;
    const int p0 = blockIdx.x * 128, nt = blockIdx.y;

    const int which = (mode == 0) ? (nt >> 3) : 3;
    const int cw    = (mode == 0) ? (nt & 7) * 128 : nt * 128;
    const float* bias = (mode == 0)
        ? ((which == 0) ? B0 : (which == 1) ? B1 : B2) : B0;
    const uint32_t* Awh = (mode == 0) ? g_xh : g_ah;
    const uint32_t* Awl = (mode == 0) ? g_xl : g_al;
    const uint32_t* wph = g_wph[which];
    const uint32_t* wpl = g_wpl[which];

    // producer coords
    const int ar = tid >> 1, ah4 = (tid & 1) * 4;
    const int bkw = tid >> 5, bn4 = (tid & 31) * 4;
    const uint32_t dAh = smem_u32(&Ah[0][ar][ah4]);
    const uint32_t dAl = smem_u32(&Al[0][ar][ah4]);
    const uint32_t dBh = smem_u32(&Bh[0][bkw][bn4]);
    const uint32_t dBl = smem_u32(&Bl[0][bkw][bn4]);
    const uint32_t abuf = 128 * APITCH * 4, bbuf = 8 * BPITCH * 4;

    auto issue = [&](int it, int buf) {
        const size_t aw = (size_t)(p0 + ar) * NW + it * 8 + ah4;
        const size_t bw = (size_t)(it * 8 + bkw) * DM + cw + bn4;
        cpa(dAh + buf * abuf, Awh + aw);
        cpa(dAl + buf * abuf, Awl + aw);
        cpa(dBh + buf * bbuf, wph + bw);
        cpa(dBl + buf * bbuf, wpl + bw);
        CP_COMMIT();
    };

    float c[4][4][4] = {};

    issue(0, 0);
    for (int it = 0; it < 64; it++) {
        const int buf = it & 1;
        if (it < 63) { issue(it + 1, buf ^ 1); CP_WAIT1(); }
        else         { CP_WAIT0(); }
        __syncthreads();

        uint32_t fa[4][4], fbh[4][2], fbl[4][2];
        #pragma unroll
        for (int mt = 0; mt < 4; mt++) {
            const int r = wm * 64 + mt * 16 + g;
            fa[mt][0] = Ah[buf][r][qd];
            fa[mt][1] = Ah[buf][r + 8][qd];
            fa[mt][2] = Ah[buf][r][qd + 4];
            fa[mt][3] = Ah[buf][r + 8][qd + 4];
        }
        #pragma unroll
        for (int nn = 0; nn < 4; nn++) {
            const int ncol = wn * 32 + nn * 8 + g;
            fbh[nn][0] = Bh[buf][qd][ncol];
            fbh[nn][1] = Bh[buf][qd + 4][ncol];
            fbl[nn][0] = Bl[buf][qd][ncol];
            fbl[nn][1] = Bl[buf][qd + 4][ncol];
        }
        #pragma unroll
        for (int mt = 0; mt < 4; mt++)
            #pragma unroll
            for (int nn = 0; nn < 4; nn++) {
                mma16(c[mt][nn], fa[mt], fbh[nn][0], fbh[nn][1]);   // hi*hi
                mma16(c[mt][nn], fa[mt], fbl[nn][0], fbl[nn][1]);   // hi*lo
            }
        #pragma unroll
        for (int mt = 0; mt < 4; mt++) {
            const int r = wm * 64 + mt * 16 + g;
            fa[mt][0] = Al[buf][r][qd];
            fa[mt][1] = Al[buf][r + 8][qd];
            fa[mt][2] = Al[buf][r][qd + 4];
            fa[mt][3] = Al[buf][r + 8][qd + 4];
        }
        #pragma unroll
        for (int mt = 0; mt < 4; mt++)
            #pragma unroll
            for (int nn = 0; nn < 4; nn++)
                mma16(c[mt][nn], fa[mt], fbh[nn][0], fbh[nn][1]);   // lo*hi
        __syncthreads();
    }

    // ---- Epilogues ----
    if (mode == 1) {
        #pragma unroll
        for (int mt = 0; mt < 4; mt++) {
            const int row = p0 + wm * 64 + mt * 16 + g;
            #pragma unroll
            for (int nn = 0; nn < 4; nn++) {
                const int col = cw + wn * 32 + nn * 8 + 2 * qd;
                const float2 bv = *(const float2*)(bias + col);
                float2 v0, v1;
                v0.x = c[mt][nn][0] + bv.x; v0.y = c[mt][nn][1] + bv.y;
                v1.x = c[mt][nn][2] + bv.x; v1.y = c[mt][nn][3] + bv.y;
                *(float2*)(oout + (size_t)row * DM + col) = v0;
                *(float2*)(oout + (size_t)(row + 8) * DM + col) = v1;
            }
        }
    } else if (which == 2) {
        // V: pack adjacent positions via shfl, store [pos-pair][col]
        #pragma unroll
        for (int mt = 0; mt < 4; mt++) {
            const int row = p0 + wm * 64 + mt * 16 + g;
            #pragma unroll
            for (int nn = 0; nn < 4; nn++) {
                const int col = cw + wn * 32 + nn * 8 + 2 * qd;
                const float2 bv = *(const float2*)(bias + col);
                float o0 = c[mt][nn][0] + bv.x, o1 = c[mt][nn][1] + bv.y;
                float o2 = c[mt][nn][2] + bv.x, o3 = c[mt][nn][3] + bv.y;
                float p0v = __shfl_xor_sync(0xffffffffu, o0, 4);
                float p1v = __shfl_xor_sync(0xffffffffu, o1, 4);
                float p2v = __shfl_xor_sync(0xffffffffu, o2, 4);
                float p3v = __shfl_xor_sync(0xffffffffu, o3, 4);
                if ((g & 1) == 0) {
                    uint32_t h0, l0, h1, l1;
                    const size_t w0 = (size_t)(row >> 1) * DM + col;
                    split2(o0, p0v, h0, l0);
                    split2(o1, p1v, h1, l1);
                    *(uint2*)(g_vh + w0) = make_uint2(h0, h1);
                    *(uint2*)(g_vl + w0) = make_uint2(l0, l1);
                    const size_t w1 = (size_t)((row + 8) >> 1) * DM + col;
                    split2(o2, p2v, h0, l0);
                    split2(o3, p3v, h1, l1);
                    *(uint2*)(g_vh + w1) = make_uint2(h0, h1);
                    *(uint2*)(g_vl + w1) = make_uint2(l0, l1);
                }
            }
        }
    } else {
        const float sc = (which == 0) ? 0.125f : 1.0f;
        uint32_t* oh = g_qh[which];
        uint32_t* ol = g_ql[which];
        #pragma unroll
        for (int mt = 0; mt < 4; mt++) {
            const int row = p0 + wm * 64 + mt * 16 + g;
            #pragma unroll
            for (int nn = 0; nn < 4; nn++) {
                const int col = cw + wn * 32 + nn * 8 + 2 * qd;
                const float2 bv = *(const float2*)(bias + col);
                const size_t w0 = (size_t)row * NW + (col >> 1);
                const size_t w1 = (size_t)(row + 8) * NW + (col >> 1);
                split2((c[mt][nn][0] + bv.x) * sc, (c[mt][nn][1] + bv.y) * sc,
                       oh[w0], ol[w0]);
                split2((c[mt][nn][2] + bv.x) * sc, (c[mt][nn][3] + bv.y) * sc,
                       oh[w1], ol[w1]);
            }
        }
    }
}

// ===========================================================================
// Flash attention bf16x3, q-tile 128, 8 warps, cp.async double-buffered K/V.
// K smem [kpos][dword] pitch 36; V smem [kword][d] pitch 72. All pure copies.
// ===========================================================================
#define KPP 36
#define VPP 72
#define KSTG (64 * KPP)          // words per K stage
#define VSTG (32 * VPP)
#define ATTN_SMEM ((2 * 2 * KSTG + 2 * 2 * VSTG) * 4)   // 73728 B

__global__ __launch_bounds__(256, 2) void attn_bf16()
{
    extern __shared__ __align__(16) uint32_t dsm[];
    uint32_t* KH = dsm;                   // [2][64][KPP]
    uint32_t* KL = KH + 2 * KSTG;
    uint32_t* VH = KL + 2 * KSTG;         // [2][32][VPP]
    uint32_t* VL = VH + 2 * VSTG;

    const int tid = threadIdx.x, lane = tid & 31, w = tid >> 5;
    const int g = lane >> 2, qd = lane & 3;
    const int qt = blockIdx.x, bh = blockIdx.y;
    const int b = bh >> 4, h = bh & 15;
    const int q0 = qt * 128;
    const int kr = tid >> 2, kq = (tid & 3) * 8;    // K loader: 2x16B
    const int vr = tid >> 3, vq = (tid & 7) * 8;    // V loader: 2x16B

    const uint32_t dK = smem_u32(KH + kr * KPP + kq);
    const uint32_t dV = smem_u32(VH + vr * VPP + vq);

    auto issue = [&](int kt, int s) {
        const int k0 = kt * 64;
        const size_t rw = (size_t)(b * SS + k0 + kr) * NW + h * 32 + kq;
        const uint32_t ks = dK + s * (KSTG * 4);
        cpa(ks,      g_qh[1] + rw);
        cpa(ks + 16, g_qh[1] + rw + 4);
        cpa(ks + 2 * KSTG * 4,      g_ql[1] + rw);
        cpa(ks + 2 * KSTG * 4 + 16, g_ql[1] + rw + 4);
        const size_t vwd = ((size_t)(b * SS + k0) >> 1) * DM + h * 64 + vq;
        const uint32_t vs = dV + s * (VSTG * 4);
        cpa(vs,      g_vh + vwd + (size_t)vr * DM);
        cpa(vs + 16, g_vh + vwd + (size_t)vr * DM + 4);
        cpa(vs + 2 * VSTG * 4,      g_vl + vwd + (size_t)vr * DM);
        cpa(vs + 2 * VSTG * 4 + 16, g_vl + vwd + (size_t)vr * DM + 4);
        CP_COMMIT();
    };

    issue(0, 0);

    // ---- Q fragments straight from global (overlapped with tile-0 loads) ----
    uint32_t qh[4][4], ql[4][4];
    {
        const size_t rw = (size_t)(b * SS + q0 + w * 16 + g) * NW + h * 32;
        const uint32_t* ph = g_qh[0] + rw;
        const uint32_t* pl = g_ql[0] + rw;
        #pragma unroll
        for (int t = 0; t < 4; t++) {
            qh[t][0] = ph[t * 8 + qd];       qh[t][1] = ph[8 * NW + t * 8 + qd];
            qh[t][2] = ph[t * 8 + qd + 4];   qh[t][3] = ph[8 * NW + t * 8 + qd + 4];
            ql[t][0] = pl[t * 8 + qd];       ql[t][1] = pl[8 * NW + t * 8 + qd];
            ql[t][2] = pl[t * 8 + qd + 4];   ql[t][3] = pl[8 * NW + t * 8 + qd + 4];
        }
    }

    float m0 = -1e30f, m1 = -1e30f, l0s = 0.f, l1s = 0.f;
    float acc[8][4] = {};

    const int nkt = 2 * qt + 2;
    for (int kt = 0; kt < nkt; kt++) {
        const int s = kt & 1;
        const int k0 = kt * 64;
        if (kt + 1 < nkt) { issue(kt + 1, s ^ 1); CP_WAIT1(); }
        else              { CP_WAIT0(); }
        __syncthreads();

        if (k0 <= q0 + w * 16 + 15) {
            const uint32_t* Ks_h = KH + s * KSTG;
            const uint32_t* Ks_l = KL + s * KSTG;
            const uint32_t* Vs_h = VH + s * VSTG;
            const uint32_t* Vs_l = VL + s * VSTG;

            // ---- S = Q K^T (Q pre-scaled), 3-term ----
            float c[8][4] = {};
            #pragma unroll
            for (int nt = 0; nt < 8; nt++) {
                #pragma unroll
                for (int t = 0; t < 4; t++) {
                    const int kc = nt * 8 + g;
                    uint32_t bh0 = Ks_h[kc * KPP + t * 8 + qd];
                    uint32_t bh1 = Ks_h[kc * KPP + t * 8 + qd + 4];
                    uint32_t bl0 = Ks_l[kc * KPP + t * 8 + qd];
                    uint32_t bl1 = Ks_l[kc * KPP + t * 8 + qd + 4];
                    mma16(c[nt], qh[t], bh0, bh1);
                    mma16(c[nt], qh[t], bl0, bl1);
                    mma16(c[nt], ql[t], bh0, bh1);
                }
            }

            // ---- causal mask ----
            if (k0 + 63 > q0 + w * 16) {
                const int qg0 = q0 + w * 16 + g, qg1 = qg0 + 8;
                #pragma unroll
                for (int nt = 0; nt < 8; nt++) {
                    const int c0 = k0 + nt * 8 + 2 * qd;
                    if (c0     > qg0) c[nt][0] = -100000.f;
                    if (c0 + 1 > qg0) c[nt][1] = -100000.f;
                    if (c0     > qg1) c[nt][2] = -100000.f;
                    if (c0 + 1 > qg1) c[nt][3] = -100000.f;
                }
            }

            // ---- online softmax ----
            float rmax0 = -1e30f, rmax1 = -1e30f;
            #pragma unroll
            for (int nt = 0; nt < 8; nt++) {
                rmax0 = fmaxf(rmax0, fmaxf(c[nt][0], c[nt][1]));
                rmax1 = fmaxf(rmax1, fmaxf(c[nt][2], c[nt][3]));
            }
            rmax0 = fmaxf(rmax0, __shfl_xor_sync(0xffffffffu, rmax0, 1));
            rmax0 = fmaxf(rmax0, __shfl_xor_sync(0xffffffffu, rmax0, 2));
            rmax1 = fmaxf(rmax1, __shfl_xor_sync(0xffffffffu, rmax1, 1));
            rmax1 = fmaxf(rmax1, __shfl_xor_sync(0xffffffffu, rmax1, 2));

            const float nm0 = fmaxf(m0, rmax0), nm1 = fmaxf(m1, rmax1);
            const float f0 = __expf(m0 - nm0), f1 = __expf(m1 - nm1);
            float s0 = 0.f, s1 = 0.f;
            #pragma unroll
            for (int nt = 0; nt < 8; nt++) {
                c[nt][0] = __expf(c[nt][0] - nm0); s0 += c[nt][0];
                c[nt][1] = __expf(c[nt][1] - nm0); s0 += c[nt][1];
                c[nt][2] = __expf(c[nt][2] - nm1); s1 += c[nt][2];
                c[nt][3] = __expf(c[nt][3] - nm1); s1 += c[nt][3];
            }
            s0 += __shfl_xor_sync(0xffffffffu, s0, 1);
            s0 += __shfl_xor_sync(0xffffffffu, s0, 2);
            s1 += __shfl_xor_sync(0xffffffffu, s1, 1);
            s1 += __shfl_xor_sync(0xffffffffu, s1, 2);
            l0s = l0s * f0 + s0; l1s = l1s * f1 + s1;
            m0 = nm0; m1 = nm1;
            #pragma unroll
            for (int dt = 0; dt < 8; dt++) {
                acc[dt][0] *= f0; acc[dt][1] *= f0;
                acc[dt][2] *= f1; acc[dt][3] *= f1;
            }

            // ---- PV, 3-term; A-frag = packed C-frag ----
            #pragma unroll
            for (int t = 0; t < 4; t++) {
                uint32_t ah[4], al[4];
                split2(c[2 * t][0],     c[2 * t][1],     ah[0], al[0]);
                split2(c[2 * t][2],     c[2 * t][3],     ah[1], al[1]);
                split2(c[2 * t + 1][0], c[2 * t + 1][1], ah[2], al[2]);
                split2(c[2 * t + 1][2], c[2 * t + 1][3], ah[3], al[3]);
                #pragma unroll
                for (int dt = 0; dt < 8; dt++) {
                    const int dc = dt * 8 + g;
                    uint32_t bh0 = Vs_h[(t * 8 + qd) * VPP + dc];
                    uint32_t bh1 = Vs_h[(t * 8 + qd + 4) * VPP + dc];
                    uint32_t bl0 = Vs_l[(t * 8 + qd) * VPP + dc];
                    uint32_t bl1 = Vs_l[(t * 8 + qd + 4) * VPP + dc];
                    mma16(acc[dt], ah, bh0, bh1);
                    mma16(acc[dt], ah, bl0, bl1);
                    mma16(acc[dt], al, bh0, bh1);
                }
            }
        }
        __syncthreads();   // all reads of stage s done before re-issue into it
    }

    // ---- normalize + write split hi/lo ----
    const float inv0 = 1.f / l0s, inv1 = 1.f / l1s;
    const size_t r0w = (size_t)(b * SS + q0 + w * 16 + g) * NW + h * 32;
    #pragma unroll
    for (int dt = 0; dt < 8; dt++) {
        const size_t w0 = r0w + dt * 4 + qd;
        const size_t w1 = w0 + 8 * NW;
        split2(acc[dt][0] * inv0, acc[dt][1] * inv0, g_ah[w0], g_al[w0]);
        split2(acc[dt][2] * inv1, acc[dt][3] * inv1, g_ah[w1], g_al[w1]);
    }
}

extern "C" void kernel_launch(void* const* d_in, const int* in_sizes, int n_in,
                              void* d_out, int out_size)
{
    const float* x  = (const float*)d_in[0];
    const float* Qw = (const float*)d_in[1];
    const float* Qb = (const float*)d_in[2];
    const float* Kw = (const float*)d_in[3];
    const float* Kb = (const float*)d_in[4];
    const float* Vw = (const float*)d_in[5];
    const float* Vb = (const float*)d_in[6];
    const float* Ow = (const float*)d_in[7];
    const float* Ob = (const float*)d_in[8];
    float* out = (float*)d_out;

    cudaFuncSetAttribute(attn_bf16,
                         cudaFuncAttributeMaxDynamicSharedMemorySize, ATTN_SMEM);

    prep_x<<<(PP * NW) / 256, 256>>>(x);
    prep_w<<<(4 * NW * DM) / 256, 256>>>(Qw, Kw, Vw, Ow);

    dim3 gq(PP / 128, 24);
    gemm_bf16<<<gq, 256>>>(Qb, Kb, Vb, nullptr, 0);

    dim3 ga(SS / 128, BB * HH);
    attn_bf16<<<ga, 256, ATTN_SMEM>>>();

    dim3 go(PP / 128, DM / 128);
    gemm_bf16<<<go, 256>>>(Ob, nullptr, nullptr, out, 1);
}